// round 1
// baseline (speedup 1.0000x reference)
#include <cuda_runtime.h>
#include <cuda_bf16.h>
#include <math.h>

// Problem constants
#define BATCH 32
#define LSEQ  128
#define TSTEPS 127          // L-1
#define HDIM  512
#define VOCAB 8000
#define NHEADS 8
#define HEADD 64
#define SKEYS 256
#define G4    2048          // 4*H
#define MROWS (BATCH*TSTEPS)   // 4064
#define ENCROWS (BATCH*SKEYS)  // 8192

// ------------------------- scratch (device globals) -------------------------
__device__ float d_emb [MROWS * HDIM];
__device__ float d_xg  [MROWS * G4];
__device__ float d_gpart[8 * G4 * BATCH];
__device__ float d_h   [BATCH * HDIM];
__device__ float d_c   [BATCH * HDIM];
__device__ float d_hs  [MROWS * HDIM];
__device__ float d_q   [MROWS * HDIM];
__device__ float d_k   [ENCROWS * HDIM];
__device__ float d_v   [ENCROWS * HDIM];
__device__ float d_ctx [MROWS * HDIM];
__device__ float d_comb[MROWS * HDIM];

// ------------------------- embedding gather -------------------------
__global__ void gather_embed_kernel(const int* __restrict__ targets,
                                    const float* __restrict__ embedding,
                                    float* __restrict__ emb) {
    int idx = blockIdx.x * blockDim.x + threadIdx.x;
    if (idx >= MROWS * HDIM) return;
    int hh = idx & (HDIM - 1);
    int bt = idx >> 9;
    int b = bt / TSTEPS;
    int t = bt - b * TSTEPS;
    int tok = targets[b * LSEQ + t];
    emb[idx] = embedding[(size_t)tok * HDIM + hh];
}

// ------------------------- init LSTM state -------------------------
__global__ void init_state_kernel(float* __restrict__ h, float* __restrict__ c) {
    int idx = blockIdx.x * blockDim.x + threadIdx.x;
    if (idx < BATCH * HDIM) { h[idx] = 0.f; c[idx] = 0.f; }
}

// ------------------------- generic SGEMM: C = A @ B^T (+bias0+bias1+add) ----
// A[M,K] row-major, B[N,K] row-major. BM=BN=128, BK=16, 256 threads, 8x8 tiles.
__global__ __launch_bounds__(256)
void sgemm_tn_kernel(const float* __restrict__ A, const float* __restrict__ B,
                     const float* __restrict__ bias0, const float* __restrict__ bias1,
                     const float* __restrict__ addsrc, float* __restrict__ C,
                     int M, int N, int K) {
    __shared__ float As[16 * 132];
    __shared__ float Bs[16 * 132];
    int tid = threadIdx.x;
    int bm = blockIdx.y, bn = blockIdx.x;
    int tx = tid & 15, ty = tid >> 4;
    int arow_base = bm * 128, bcol_base = bn * 128;

    float acc[8][8];
#pragma unroll
    for (int i = 0; i < 8; i++)
#pragma unroll
        for (int j = 0; j < 8; j++) acc[i][j] = 0.f;

    for (int k0 = 0; k0 < K; k0 += 16) {
#pragma unroll
        for (int i = 0; i < 2; i++) {
            int f = tid + i * 256;
            int r = f >> 2, kq = (f & 3) << 2;
            int grow = arow_base + r;
            float4 v = make_float4(0.f, 0.f, 0.f, 0.f);
            if (grow < M) v = *(const float4*)(A + (size_t)grow * K + k0 + kq);
            As[(kq + 0) * 132 + r] = v.x;
            As[(kq + 1) * 132 + r] = v.y;
            As[(kq + 2) * 132 + r] = v.z;
            As[(kq + 3) * 132 + r] = v.w;
        }
#pragma unroll
        for (int i = 0; i < 2; i++) {
            int f = tid + i * 256;
            int r = f >> 2, kq = (f & 3) << 2;
            int grow = bcol_base + r;
            float4 v = make_float4(0.f, 0.f, 0.f, 0.f);
            if (grow < N) v = *(const float4*)(B + (size_t)grow * K + k0 + kq);
            Bs[(kq + 0) * 132 + r] = v.x;
            Bs[(kq + 1) * 132 + r] = v.y;
            Bs[(kq + 2) * 132 + r] = v.z;
            Bs[(kq + 3) * 132 + r] = v.w;
        }
        __syncthreads();
#pragma unroll
        for (int kk = 0; kk < 16; kk++) {
            float a[8], bv[8];
            float4 a0 = *(const float4*)&As[kk * 132 + ty * 8];
            float4 a1 = *(const float4*)&As[kk * 132 + ty * 8 + 4];
            float4 b0 = *(const float4*)&Bs[kk * 132 + tx * 8];
            float4 b1 = *(const float4*)&Bs[kk * 132 + tx * 8 + 4];
            a[0]=a0.x; a[1]=a0.y; a[2]=a0.z; a[3]=a0.w; a[4]=a1.x; a[5]=a1.y; a[6]=a1.z; a[7]=a1.w;
            bv[0]=b0.x; bv[1]=b0.y; bv[2]=b0.z; bv[3]=b0.w; bv[4]=b1.x; bv[5]=b1.y; bv[6]=b1.z; bv[7]=b1.w;
#pragma unroll
            for (int i = 0; i < 8; i++)
#pragma unroll
                for (int j = 0; j < 8; j++) acc[i][j] += a[i] * bv[j];
        }
        __syncthreads();
    }

#pragma unroll
    for (int i = 0; i < 8; i++) {
        int row = arow_base + ty * 8 + i;
        if (row >= M) continue;
#pragma unroll
        for (int j = 0; j < 8; j++) {
            int col = bcol_base + tx * 8 + j;
            if (col >= N) continue;
            float v = acc[i][j];
            if (bias0) v += bias0[col];
            if (bias1) v += bias1[col];
            if (addsrc) v += addsrc[(size_t)row * N + col];
            C[(size_t)row * N + col] = v;
        }
    }
}

// ------------------------- LSTM recurrent GEMM (K-split partials) ----------
// gpart[ks][row][b] = sum_{k in slice ks} w_hh[row][k] * h[b][k]
// grid (16 row-tiles of 128, 8 k-slices of 64), 256 threads, 4x4 tiles.
__global__ __launch_bounds__(256)
void lstm_gemm_kernel(const float* __restrict__ h, const float* __restrict__ w_hh,
                      float* __restrict__ gpart) {
    __shared__ float Ws[128 * 65];
    __shared__ float Hs[64 * 36];
    int tid = threadIdx.x;
    int r0 = blockIdx.x * 128;
    int kbase = blockIdx.y * 64;

#pragma unroll
    for (int i = 0; i < 8; i++) {
        int f = tid + i * 256;
        int row = f >> 4;
        int kq = (f & 15) << 2;
        float4 w4 = *(const float4*)(w_hh + (size_t)(r0 + row) * HDIM + kbase + kq);
        float* p = &Ws[row * 65 + kq];
        p[0] = w4.x; p[1] = w4.y; p[2] = w4.z; p[3] = w4.w;
    }
#pragma unroll
    for (int i = 0; i < 2; i++) {
        int f = tid + i * 256;
        int b = f >> 4;
        int kq = (f & 15) << 2;
        float4 h4 = *(const float4*)(h + b * HDIM + kbase + kq);
        Hs[(kq + 0) * 36 + b] = h4.x;
        Hs[(kq + 1) * 36 + b] = h4.y;
        Hs[(kq + 2) * 36 + b] = h4.z;
        Hs[(kq + 3) * 36 + b] = h4.w;
    }
    __syncthreads();

    int tr = tid & 31;
    int tb = tid >> 5;
    float acc[4][4];
#pragma unroll
    for (int u = 0; u < 4; u++)
#pragma unroll
        for (int v = 0; v < 4; v++) acc[u][v] = 0.f;

#pragma unroll 8
    for (int kk = 0; kk < 64; kk++) {
        float w0 = Ws[(tr      ) * 65 + kk];
        float w1 = Ws[(tr + 32 ) * 65 + kk];
        float w2 = Ws[(tr + 64 ) * 65 + kk];
        float w3 = Ws[(tr + 96 ) * 65 + kk];
        float4 hv = *(const float4*)&Hs[kk * 36 + tb * 4];
        acc[0][0] += w0 * hv.x; acc[0][1] += w0 * hv.y; acc[0][2] += w0 * hv.z; acc[0][3] += w0 * hv.w;
        acc[1][0] += w1 * hv.x; acc[1][1] += w1 * hv.y; acc[1][2] += w1 * hv.z; acc[1][3] += w1 * hv.w;
        acc[2][0] += w2 * hv.x; acc[2][1] += w2 * hv.y; acc[2][2] += w2 * hv.z; acc[2][3] += w2 * hv.w;
        acc[3][0] += w3 * hv.x; acc[3][1] += w3 * hv.y; acc[3][2] += w3 * hv.z; acc[3][3] += w3 * hv.w;
    }

    int ks = blockIdx.y;
#pragma unroll
    for (int u = 0; u < 4; u++) {
        int row = r0 + tr + 32 * u;
        float4 o = make_float4(acc[u][0], acc[u][1], acc[u][2], acc[u][3]);
        *(float4*)(gpart + ((size_t)ks * G4 + row) * BATCH + tb * 4) = o;
    }
}

// ------------------------- LSTM gate/update --------------------------------
__global__ void lstm_gate_kernel(const float* __restrict__ gpart,
                                 const float* __restrict__ xg,
                                 float* __restrict__ c, float* __restrict__ h,
                                 float* __restrict__ hs, int t) {
    int gid = blockIdx.x * blockDim.x + threadIdx.x;
    if (gid >= BATCH * HDIM) return;
    int b = gid & 31;
    int hd = gid >> 5;
    size_t btrow = (size_t)(b * TSTEPS + t);
    float gsum[4];
#pragma unroll
    for (int q = 0; q < 4; q++) {
        int row = q * HDIM + hd;
        float s = 0.f;
#pragma unroll
        for (int ks = 0; ks < 8; ks++)
            s += gpart[((size_t)ks * G4 + row) * BATCH + b];
        gsum[q] = s + xg[btrow * G4 + row];
    }
    float i_ = 1.f / (1.f + expf(-gsum[0]));
    float f_ = 1.f / (1.f + expf(-gsum[1]));
    float g_ = tanhf(gsum[2]);
    float o_ = 1.f / (1.f + expf(-gsum[3]));
    int sidx = b * HDIM + hd;
    float cn = f_ * c[sidx] + i_ * g_;
    float hn = o_ * tanhf(cn);
    c[sidx] = cn;
    h[sidx] = hn;
    hs[btrow * HDIM + hd] = hn;
}

// ------------------------- fused attention ---------------------------------
// One block per (b, head). K,V in dynamic smem (stride 65). Warp-per-query.
__global__ __launch_bounds__(256)
void attn_kernel(const float* __restrict__ q, const float* __restrict__ kb,
                 const float* __restrict__ vb, float* __restrict__ ctx) {
    extern __shared__ float sm[];
    float* Ks = sm;                  // 256*65
    float* Vs = Ks + 256 * 65;       // 256*65
    float* qs = Vs + 256 * 65;       // 8*64
    float* ps = qs + 8 * 64;         // 8*256
    int tid = threadIdx.x;
    int b = blockIdx.x >> 3, hh = blockIdx.x & 7;
    const float* kbase = kb + (size_t)b * SKEYS * HDIM + hh * HEADD;
    const float* vbase = vb + (size_t)b * SKEYS * HDIM + hh * HEADD;

    for (int idx = tid; idx < SKEYS * HEADD; idx += 256) {
        int s = idx >> 6, d = idx & 63;
        Ks[s * 65 + d] = kbase[(size_t)s * HDIM + d];
        Vs[s * 65 + d] = vbase[(size_t)s * HDIM + d];
    }
    __syncthreads();

    int w = tid >> 5, l = tid & 31;
    for (int q0 = 0; q0 < TSTEPS; q0 += 8) {
        for (int idx = tid; idx < 8 * HEADD; idx += 256) {
            int qi = idx >> 6, d = idx & 63;
            int qq = q0 + qi;
            qs[idx] = (qq < TSTEPS) ? q[(size_t)(b * TSTEPS + qq) * HDIM + hh * HEADD + d] : 0.f;
        }
        __syncthreads();
        int qq = q0 + w;
        if (qq < TSTEPS) {
            float sc[8];
#pragma unroll
            for (int ki = 0; ki < 8; ki++) {
                int s = l + (ki << 5);
                float dot = 0.f;
#pragma unroll
                for (int d = 0; d < HEADD; d++)
                    dot += qs[w * 64 + d] * Ks[s * 65 + d];
                sc[ki] = dot * 0.125f;
            }
            float m = sc[0];
#pragma unroll
            for (int ki = 1; ki < 8; ki++) m = fmaxf(m, sc[ki]);
#pragma unroll
            for (int o = 16; o > 0; o >>= 1) m = fmaxf(m, __shfl_xor_sync(0xffffffffu, m, o));
            float sum = 0.f;
#pragma unroll
            for (int ki = 0; ki < 8; ki++) { sc[ki] = expf(sc[ki] - m); sum += sc[ki]; }
#pragma unroll
            for (int o = 16; o > 0; o >>= 1) sum += __shfl_xor_sync(0xffffffffu, sum, o);
            float inv = 1.f / sum;
#pragma unroll
            for (int ki = 0; ki < 8; ki++) ps[w * 256 + l + (ki << 5)] = sc[ki] * inv;
            __syncwarp();
            float a0 = 0.f, a1 = 0.f;
#pragma unroll 4
            for (int s = 0; s < SKEYS; s++) {
                float pw = ps[w * 256 + s];
                a0 += pw * Vs[s * 65 + l];
                a1 += pw * Vs[s * 65 + l + 32];
            }
            size_t obase = (size_t)(b * TSTEPS + qq) * HDIM + hh * HEADD;
            ctx[obase + l] = a0;
            ctx[obase + l + 32] = a1;
        }
        __syncthreads();
    }
}

// ------------------------- launch ------------------------------------------
static const int ATTN_SMEM = (2 * 256 * 65 + 8 * 64 + 8 * 256) * (int)sizeof(float);

extern "C" void kernel_launch(void* const* d_in, const int* in_sizes, int n_in,
                              void* d_out, int out_size) {
    const int*   targets    = (const int*)  d_in[0];
    const float* enc        = (const float*)d_in[1];
    const float* embedding  = (const float*)d_in[2];
    const float* w_ih       = (const float*)d_in[3];
    const float* w_hh       = (const float*)d_in[4];
    const float* b_ih       = (const float*)d_in[5];
    const float* b_hh       = (const float*)d_in[6];
    const float* in_proj_w  = (const float*)d_in[7];
    const float* in_proj_b  = (const float*)d_in[8];
    const float* out_proj_w = (const float*)d_in[9];
    const float* out_proj_b = (const float*)d_in[10];
    const float* fc_w       = (const float*)d_in[11];
    const float* fc_b       = (const float*)d_in[12];
    float* out = (float*)d_out;

    float *emb, *xg, *gpart, *h, *c, *hs, *qb, *kk, *vv, *ctx, *comb;
    cudaGetSymbolAddress((void**)&emb,   d_emb);
    cudaGetSymbolAddress((void**)&xg,    d_xg);
    cudaGetSymbolAddress((void**)&gpart, d_gpart);
    cudaGetSymbolAddress((void**)&h,     d_h);
    cudaGetSymbolAddress((void**)&c,     d_c);
    cudaGetSymbolAddress((void**)&hs,    d_hs);
    cudaGetSymbolAddress((void**)&qb,    d_q);
    cudaGetSymbolAddress((void**)&kk,    d_k);
    cudaGetSymbolAddress((void**)&vv,    d_v);
    cudaGetSymbolAddress((void**)&ctx,   d_ctx);
    cudaGetSymbolAddress((void**)&comb,  d_comb);

    cudaFuncSetAttribute(attn_kernel, cudaFuncAttributeMaxDynamicSharedMemorySize, ATTN_SMEM);

    // 1. embedding gather
    {
        int n = MROWS * HDIM;
        gather_embed_kernel<<<(n + 255) / 256, 256>>>(targets, embedding, emb);
    }
    // 2. xg = emb @ w_ih^T + b_ih + b_hh
    {
        dim3 grid(G4 / 128, (MROWS + 127) / 128);
        sgemm_tn_kernel<<<grid, 256>>>(emb, w_ih, b_ih, b_hh, nullptr, xg, MROWS, G4, HDIM);
    }
    // 3. init state
    init_state_kernel<<<(BATCH * HDIM + 255) / 256, 256>>>(h, c);
    // 4. LSTM scan
    for (int t = 0; t < TSTEPS; t++) {
        lstm_gemm_kernel<<<dim3(16, 8), 256>>>(h, w_hh, gpart);
        lstm_gate_kernel<<<(BATCH * HDIM + 255) / 256, 256>>>(gpart, xg, c, h, hs, t);
    }
    // 5. q projection
    {
        dim3 grid(HDIM / 128, (MROWS + 127) / 128);
        sgemm_tn_kernel<<<grid, 256>>>(hs, in_proj_w, in_proj_b, nullptr, nullptr, qb, MROWS, HDIM, HDIM);
    }
    // 6. k projection
    {
        dim3 grid(HDIM / 128, ENCROWS / 128);
        sgemm_tn_kernel<<<grid, 256>>>(enc, in_proj_w + (size_t)HDIM * HDIM,
                                       in_proj_b + HDIM, nullptr, nullptr, kk, ENCROWS, HDIM, HDIM);
    }
    // 7. v projection
    {
        dim3 grid(HDIM / 128, ENCROWS / 128);
        sgemm_tn_kernel<<<grid, 256>>>(enc, in_proj_w + (size_t)2 * HDIM * HDIM,
                                       in_proj_b + 2 * HDIM, nullptr, nullptr, vv, ENCROWS, HDIM, HDIM);
    }
    // 8. attention
    attn_kernel<<<BATCH * NHEADS, 256, ATTN_SMEM>>>(qb, kk, vv, ctx);
    // 9. out projection + residual (lstm_out)
    {
        dim3 grid(HDIM / 128, (MROWS + 127) / 128);
        sgemm_tn_kernel<<<grid, 256>>>(ctx, out_proj_w, out_proj_b, nullptr, hs, comb, MROWS, HDIM, HDIM);
    }
    // 10. fc
    {
        dim3 grid((VOCAB + 127) / 128, (MROWS + 127) / 128);
        sgemm_tn_kernel<<<grid, 256>>>(comb, fc_w, fc_b, nullptr, nullptr, out, MROWS, VOCAB, HDIM);
    }
}